// round 3
// baseline (speedup 1.0000x reference)
#include <cuda_runtime.h>
#include <math.h>

#define B_  8
#define H_  384
#define W_  512
#define HW_ (H_ * W_)
#define NPIX (B_ * HW_)

#define K0 (-1.0f / 12.0f)
#define K1 (2.0f / 3.0f)
#define K3 (-2.0f / 3.0f)
#define K4 (1.0f / 12.0f)

// ---- scratch (module globals; 16B aligned for float4 access) ----
__device__ __align__(16) float  g_flowf[B_ * 2 * HW_];
__device__ __align__(16) float  g_flowb[B_ * 2 * HW_];
__device__ __align__(16) float  g_imgw [B_ * 3 * HW_];
__device__ __align__(16) float  g_mask [NPIX];
__device__ double g_acc[3];   // 0 = energy, 1 = entropy-sum, 2 = epe-sum

__device__ __forceinline__ float sigm(float x) { return 1.0f / (1.0f + __expf(-x)); }

__device__ __forceinline__ void ld4a(const float* __restrict__ p, float* a) {
    float4 v = *reinterpret_cast<const float4*>(p);
    a[0] = v.x; a[1] = v.y; a[2] = v.z; a[3] = v.w;
}
__device__ __forceinline__ void st4a(float* p, const float* a) {
    float4 v; v.x = a[0]; v.y = a[1]; v.z = a[2]; v.w = a[3];
    *reinterpret_cast<float4*>(p) = v;
}
// d = A - W (float4)
__device__ __forceinline__ void diff4(const float* __restrict__ pa,
                                      const float* __restrict__ pw, float* d) {
    float4 a = *reinterpret_cast<const float4*>(pa);
    float4 w = *reinterpret_cast<const float4*>(pw);
    d[0] = a.x - w.x; d[1] = a.y - w.y; d[2] = a.z - w.z; d[3] = a.w - w.w;
}
__device__ __forceinline__ void zero4(float* d) { d[0]=d[1]=d[2]=d[3]=0.0f; }

__device__ __forceinline__ void blockReduceAdd(double* dst, float v) {
    __shared__ float ws[32];
    int lane = threadIdx.x & 31;
    int wid  = threadIdx.x >> 5;
#pragma unroll
    for (int o = 16; o; o >>= 1) v += __shfl_down_sync(0xffffffffu, v, o);
    __syncthreads();
    if (lane == 0) ws[wid] = v;
    __syncthreads();
    if (wid == 0) {
        int nw = (blockDim.x + 31) >> 5;
        v = (lane < nw) ? ws[lane] : 0.0f;
#pragma unroll
        for (int o = 16; o; o >>= 1) v += __shfl_down_sync(0xffffffffu, v, o);
        if (lane == 0) atomicAdd(dst, (double)v);
    }
}

__global__ void zero_acc_kernel() {
    if (threadIdx.x < 3) g_acc[threadIdx.x] = 0.0;
}

// Pass 1: flow samples + entropy + EPE, 4 px/thread
__global__ void sample_kernel(const float* __restrict__ mf, const float* __restrict__ lvf,
                              const float* __restrict__ nf,
                              const float* __restrict__ mb, const float* __restrict__ lvb,
                              const float* __restrict__ nb,
                              const float* __restrict__ tgt) {
    int t = blockIdx.x * blockDim.x + threadIdx.x;     // 0 .. NPIX/4-1 exactly
    int b  = t / (HW_ / 4);
    int r4 = t - b * (HW_ / 4);
    int i0 = b * 2 * HW_ + r4 * 4;
    int i1 = i0 + HW_;

    float m0[4], m1[4], l0[4], l1[4], n0[4], n1[4], t0[4], t1[4];
    ld4a(mf  + i0, m0); ld4a(mf  + i1, m1);
    ld4a(lvf + i0, l0); ld4a(lvf + i1, l1);
    ld4a(nf  + i0, n0); ld4a(nf  + i1, n1);
    ld4a(tgt + i0, t0); ld4a(tgt + i1, t1);

    float f0[4], f1[4];
    float ent = 0.0f, epe = 0.0f;
#pragma unroll
    for (int i = 0; i < 4; i++) {
        f0[i] = m0[i] + __expf(0.5f * l0[i]) * n0[i];
        f1[i] = m1[i] + __expf(0.5f * l1[i]) * n1[i];
        ent += l0[i] + l1[i];
        float d0 = m0[i] - t0[i], d1 = m1[i] - t1[i];
        epe += sqrtf(d0 * d0 + d1 * d1);
    }
    st4a(g_flowf + i0, f0); st4a(g_flowf + i1, f1);

    ld4a(mb  + i0, m0); ld4a(mb  + i1, m1);
    ld4a(lvb + i0, l0); ld4a(lvb + i1, l1);
    ld4a(nb  + i0, n0); ld4a(nb  + i1, n1);
#pragma unroll
    for (int i = 0; i < 4; i++) {
        f0[i] = m0[i] + __expf(0.5f * l0[i]) * n0[i];
        f1[i] = m1[i] + __expf(0.5f * l1[i]) * n1[i];
        ent += l0[i] + l1[i];
    }
    st4a(g_flowb + i0, f0); st4a(g_flowb + i1, f1);

    blockReduceAdd(&g_acc[1], ent);
    blockReduceAdd(&g_acc[2], epe);
}

// Pass 2: per-direction energy terms, 4 px/thread (one block per image row)
__global__ void dir_kernel(const float* __restrict__ img_a,
                           const float* __restrict__ img_b, int dirn) {
    const float* __restrict__ flow_a = dirn ? g_flowb : g_flowf;
    const float* __restrict__ flow_b = dirn ? g_flowf : g_flowb;
    int row = blockIdx.x;              // b*H + y
    int b = row / H_;
    int y = row - b * H_;
    int x = threadIdx.x * 4;
    int rbase = y * W_ + x;

    const float* fa  = flow_a + (size_t)b * 2 * HW_;
    const float* fb0 = flow_b + (size_t)b * 2 * HW_;
    const float* fb1 = fb0 + HW_;
    const float* ia  = img_a + (size_t)b * 3 * HW_;
    const float* ib  = img_b + (size_t)b * 3 * HW_;

    float fa0[4], fa1[4];
    ld4a(fa + rbase, fa0);
    ld4a(fa + HW_ + rbase, fa1);
    float fa0r = 0.0f, fa1r = 0.0f;
    if (x + 4 < W_) { fa0r = fa[rbase + 4]; fa1r = fa[HW_ + rbase + 4]; }
    bool hasD = (y < H_ - 1);
    float fd0[4], fd1[4];
    if (hasD) { ld4a(fa + rbase + W_, fd0); ld4a(fa + HW_ + rbase + W_, fd1); }
    else      { zero4(fd0); zero4(fd1); }

    float ia0[4], ia1[4], ia2[4];
    ld4a(ia + rbase, ia0);
    ld4a(ia + HW_ + rbase, ia1);
    ld4a(ia + 2 * HW_ + rbase, ia2);

    float mout[4], w0out[4], w1out[4], w2out[4];
    float e = 0.0f;

#pragma unroll
    for (int i = 0; i < 4; i++) {
        float f0 = fa0[i], f1 = fa1[i];
        float xq = (float)(x + i) + f0;
        float yq = (float)y + f1;

        float mx = sigm(xq + 0.5f) * (1.0f - sigm(xq - ((float)W_ - 0.5f)));
        float my = sigm(yq + 0.5f) * (1.0f - sigm(yq - ((float)H_ - 0.5f)));
        float bmask = mx * my;

        float x0f = floorf(xq), y0f = floorf(yq);
        float wx = xq - x0f, wy = yq - y0f;
        int x0 = (int)x0f, y0 = (int)y0f;
        int x1 = x0 + 1,   y1 = y0 + 1;
        float vx0 = (x0 >= 0 && x0 <= W_ - 1) ? 1.0f : 0.0f;
        float vx1 = (x1 >= 0 && x1 <= W_ - 1) ? 1.0f : 0.0f;
        float vy0 = (y0 >= 0 && y0 <= H_ - 1) ? 1.0f : 0.0f;
        float vy1 = (y1 >= 0 && y1 <= H_ - 1) ? 1.0f : 0.0f;
        float w00 = (1.0f - wx) * (1.0f - wy) * vx0 * vy0;
        float w10 = wx * (1.0f - wy) * vx1 * vy0;
        float w01 = (1.0f - wx) * wy * vx0 * vy1;
        float w11 = wx * wy * vx1 * vy1;
        int xc0 = min(max(x0, 0), W_ - 1), xc1 = min(max(x1, 0), W_ - 1);
        int yc0 = min(max(y0, 0), H_ - 1), yc1 = min(max(y1, 0), H_ - 1);
        int o00 = yc0 * W_ + xc0, o10 = yc0 * W_ + xc1;
        int o01 = yc1 * W_ + xc0, o11 = yc1 * W_ + xc1;

        float fw0 = w00 * fb0[o00] + w10 * fb0[o10] + w01 * fb0[o01] + w11 * fb0[o11];
        float fw1 = w00 * fb1[o00] + w10 * fb1[o10] + w01 * fb1[o01] + w11 * fb1[o11];

        float mag = f0 * f0 + f1 * f1 + fw0 * fw0 + fw1 * fw1;
        float d0 = f0 + fw0, d1 = f1 + fw1;
        float D = d0 * d0 + d1 * d1;
        float occ = 1.0f - sigm(D - (0.01f * mag + 0.5f));
        float m = bmask * occ;
        mout[i] = m;

        const float* ibc0 = ib;
        const float* ibc1 = ib + HW_;
        const float* ibc2 = ib + 2 * HW_;
        float v0 = w00 * ibc0[o00] + w10 * ibc0[o10] + w01 * ibc0[o01] + w11 * ibc0[o11];
        float v1 = w00 * ibc1[o00] + w10 * ibc1[o10] + w01 * ibc1[o01] + w11 * ibc1[o11];
        float v2 = w00 * ibc2[o00] + w10 * ibc2[o10] + w01 * ibc2[o01] + w11 * ibc2[o11];
        w0out[i] = v0; w1out[i] = v1; w2out[i] = v2;

        float da0 = ia0[i] - v0, da1 = ia1[i] - v1, da2 = ia2[i] - v2;
        float A = da0 * da0 + da1 * da1 + da2 * da2;

        e += (1.0f - m) + sqrtf(A + 1e-5f) * m + sqrtf(D + 1e-5f) * m;

        float s = 0.0f;
        if (x + i < W_ - 1) {
            float nx0 = (i < 3) ? fa0[i + 1] : fa0r;
            float nx1 = (i < 3) ? fa1[i + 1] : fa1r;
            float a0 = nx0 - f0, a1 = nx1 - f1;
            s += a0 * a0 + a1 * a1;
        }
        if (hasD) {
            float a0 = fd0[i] - f0, a1 = fd1[i] - f1;
            s += a0 * a0 + a1 * a1;
        }
        e += sqrtf(s + 1e-5f);
    }

    st4a(g_mask + (size_t)b * HW_ + rbase, mout);
    float* iw = g_imgw + (size_t)b * 3 * HW_;
    st4a(iw + rbase, w0out);
    st4a(iw + HW_ + rbase, w1out);
    st4a(iw + 2 * HW_ + rbase, w2out);

    blockReduceAdd(&g_acc[0], e);
}

// Pass 3: 5-tap gradient-constancy term. Uses filt(A)-filt(W) = filt(A-W).
__global__ void grad_kernel(const float* __restrict__ img_a) {
    int row = blockIdx.x;
    int b = row / H_;
    int y = row - b * H_;
    int x = threadIdx.x * 4;
    int rbase = y * W_ + x;

    const float* ia = img_a + (size_t)b * 3 * HW_;
    const float* iw = g_imgw + (size_t)b * 3 * HW_;
    float m[4];
    ld4a(g_mask + (size_t)b * HW_ + rbase, m);

    bool hasL  = (x >= 4);
    bool hasR  = (x + 4 < W_);
    bool hasU2 = (y >= 2), hasU1 = (y >= 1);
    bool hasD1 = (y + 1 < H_), hasD2 = (y + 2 < H_);

    float Ct[4] = {0.0f, 0.0f, 0.0f, 0.0f};
#pragma unroll
    for (int c = 0; c < 3; c++) {
        const float* A  = ia + c * HW_;
        const float* Wp = iw + c * HW_;
        int o = rbase;
        float dC[4], dL[4], dR[4], dU2[4], dU1[4], dD1[4], dD2[4];
        diff4(A + o, Wp + o, dC);
        if (hasL)  diff4(A + o - 4, Wp + o - 4, dL);           else zero4(dL);
        if (hasR)  diff4(A + o + 4, Wp + o + 4, dR);           else zero4(dR);
        if (hasU2) diff4(A + o - 2 * W_, Wp + o - 2 * W_, dU2); else zero4(dU2);
        if (hasU1) diff4(A + o - W_,     Wp + o - W_,     dU1); else zero4(dU1);
        if (hasD1) diff4(A + o + W_,     Wp + o + W_,     dD1); else zero4(dD1);
        if (hasD2) diff4(A + o + 2 * W_, Wp + o + 2 * W_, dD2); else zero4(dD2);

        float gx0 = K0 * dL[2] + K1 * dL[3] + K3 * dC[1] + K4 * dC[2];
        float gx1 = K0 * dL[3] + K1 * dC[0] + K3 * dC[2] + K4 * dC[3];
        float gx2 = K0 * dC[0] + K1 * dC[1] + K3 * dC[3] + K4 * dR[0];
        float gx3 = K0 * dC[1] + K1 * dC[2] + K3 * dR[0] + K4 * dR[1];
        Ct[0] += gx0 * gx0; Ct[1] += gx1 * gx1;
        Ct[2] += gx2 * gx2; Ct[3] += gx3 * gx3;

#pragma unroll
        for (int i = 0; i < 4; i++) {
            float gy = K0 * dU2[i] + K1 * dU1[i] + K3 * dD1[i] + K4 * dD2[i];
            Ct[i] += gy * gy;
        }
    }

    float e = 0.0f;
#pragma unroll
    for (int i = 0; i < 4; i++) e += sqrtf(Ct[i] + 1e-5f) * m[i];

    blockReduceAdd(&g_acc[0], e);
}

__global__ void finalize_kernel(float* __restrict__ out) {
    if (threadIdx.x == 0) {
        double energy  = g_acc[0];
        double entropy = 0.5 * g_acc[1];
        out[0] = (float)((energy - entropy) / (double)B_);
        out[1] = (float)(g_acc[2] / (double)NPIX);
    }
}

extern "C" void kernel_launch(void* const* d_in, const int* in_sizes, int n_in,
                              void* d_out, int out_size) {
    const float* meanf   = (const float*)d_in[0];
    const float* logvarf = (const float*)d_in[1];
    const float* meanb   = (const float*)d_in[2];
    const float* logvarb = (const float*)d_in[3];
    const float* img1    = (const float*)d_in[4];
    const float* img2    = (const float*)d_in[5];
    const float* target  = (const float*)d_in[6];
    const float* noisef  = (const float*)d_in[7];
    const float* noiseb  = (const float*)d_in[8];
    float* out = (float*)d_out;

    zero_acc_kernel<<<1, 32>>>();
    sample_kernel<<<NPIX / 4 / 256, 256>>>(meanf, logvarf, noisef,
                                           meanb, logvarb, noiseb, target);
    dir_kernel<<<B_ * H_, W_ / 4>>>(img1, img2, 0);
    grad_kernel<<<B_ * H_, W_ / 4>>>(img1);
    dir_kernel<<<B_ * H_, W_ / 4>>>(img2, img1, 1);
    grad_kernel<<<B_ * H_, W_ / 4>>>(img2);
    finalize_kernel<<<1, 32>>>(out);
}

// round 4
// speedup vs baseline: 1.4110x; 1.4110x over previous
#include <cuda_runtime.h>
#include <math.h>

#define B_  8
#define H_  384
#define W_  512
#define HW_ (H_ * W_)
#define NPIX (B_ * HW_)

#define K0 (-1.0f / 12.0f)
#define K1 (2.0f / 3.0f)
#define K3 (-2.0f / 3.0f)
#define K4 (1.0f / 12.0f)

// ---- scratch (module globals; 16B aligned for float4 access) ----
__device__ __align__(16) float  g_flowf[B_ * 2 * HW_];
__device__ __align__(16) float  g_flowb[B_ * 2 * HW_];
__device__ __align__(16) float  g_diff [B_ * 3 * HW_];   // img_a - warp(img_b)
__device__ __align__(16) float  g_mask [NPIX];
__device__ double g_acc[3];   // 0 = energy, 1 = entropy-sum, 2 = epe-sum

__device__ __forceinline__ float sigm(float x) { return 1.0f / (1.0f + __expf(-x)); }

__device__ __forceinline__ void ld4a(const float* __restrict__ p, float* a) {
    float4 v = *reinterpret_cast<const float4*>(p);
    a[0] = v.x; a[1] = v.y; a[2] = v.z; a[3] = v.w;
}
__device__ __forceinline__ void st4a(float* p, const float* a) {
    float4 v; v.x = a[0]; v.y = a[1]; v.z = a[2]; v.w = a[3];
    *reinterpret_cast<float4*>(p) = v;
}
__device__ __forceinline__ void zero4(float* d) { d[0]=d[1]=d[2]=d[3]=0.0f; }

__device__ __forceinline__ void blockReduceAdd(double* dst, float v) {
    __shared__ float ws[32];
    int lane = threadIdx.x & 31;
    int wid  = threadIdx.x >> 5;
#pragma unroll
    for (int o = 16; o; o >>= 1) v += __shfl_down_sync(0xffffffffu, v, o);
    __syncthreads();
    if (lane == 0) ws[wid] = v;
    __syncthreads();
    if (wid == 0) {
        int nw = (blockDim.x + 31) >> 5;
        v = (lane < nw) ? ws[lane] : 0.0f;
#pragma unroll
        for (int o = 16; o; o >>= 1) v += __shfl_down_sync(0xffffffffu, v, o);
        if (lane == 0) atomicAdd(dst, (double)v);
    }
}

__global__ void zero_acc_kernel() {
    if (threadIdx.x < 3) g_acc[threadIdx.x] = 0.0;
}

// Pass 1: flow samples + entropy + EPE, 4 px/thread, float4
__global__ void sample_kernel(const float* __restrict__ mf, const float* __restrict__ lvf,
                              const float* __restrict__ nf,
                              const float* __restrict__ mb, const float* __restrict__ lvb,
                              const float* __restrict__ nb,
                              const float* __restrict__ tgt) {
    int t = blockIdx.x * blockDim.x + threadIdx.x;     // 0 .. NPIX/4-1 exactly
    int b  = t / (HW_ / 4);
    int r4 = t - b * (HW_ / 4);
    int i0 = b * 2 * HW_ + r4 * 4;
    int i1 = i0 + HW_;

    float m0[4], m1[4], l0[4], l1[4], n0[4], n1[4], t0[4], t1[4];
    ld4a(mf  + i0, m0); ld4a(mf  + i1, m1);
    ld4a(lvf + i0, l0); ld4a(lvf + i1, l1);
    ld4a(nf  + i0, n0); ld4a(nf  + i1, n1);
    ld4a(tgt + i0, t0); ld4a(tgt + i1, t1);

    float f0[4], f1[4];
    float ent = 0.0f, epe = 0.0f;
#pragma unroll
    for (int i = 0; i < 4; i++) {
        f0[i] = m0[i] + __expf(0.5f * l0[i]) * n0[i];
        f1[i] = m1[i] + __expf(0.5f * l1[i]) * n1[i];
        ent += l0[i] + l1[i];
        float d0 = m0[i] - t0[i], d1 = m1[i] - t1[i];
        epe += sqrtf(d0 * d0 + d1 * d1);
    }
    st4a(g_flowf + i0, f0); st4a(g_flowf + i1, f1);

    ld4a(mb  + i0, m0); ld4a(mb  + i1, m1);
    ld4a(lvb + i0, l0); ld4a(lvb + i1, l1);
    ld4a(nb  + i0, n0); ld4a(nb  + i1, n1);
#pragma unroll
    for (int i = 0; i < 4; i++) {
        f0[i] = m0[i] + __expf(0.5f * l0[i]) * n0[i];
        f1[i] = m1[i] + __expf(0.5f * l1[i]) * n1[i];
        ent += l0[i] + l1[i];
    }
    st4a(g_flowb + i0, f0); st4a(g_flowb + i1, f1);

    blockReduceAdd(&g_acc[1], ent);
    blockReduceAdd(&g_acc[2], epe);
}

// Pass 2 (per direction): 1 px/thread. Stores mask and photometric DIFF
// (img_a - warp(img_b)) to scratch for the gradient pass.
__global__ void dir_kernel(const float* __restrict__ img_a,
                           const float* __restrict__ img_b, int dirn) {
    const float* __restrict__ flow_a = dirn ? g_flowb : g_flowf;
    const float* __restrict__ flow_b = dirn ? g_flowf : g_flowb;
    int p = blockIdx.x * blockDim.x + threadIdx.x;   // grid covers NPIX exactly
    int b = p / HW_;
    int r = p - b * HW_;
    int y = r / W_;
    int x = r - y * W_;
    int base2 = b * 2 * HW_ + r;

    float fa0 = flow_a[base2];
    float fa1 = flow_a[base2 + HW_];
    float xq = (float)x + fa0;
    float yq = (float)y + fa1;

    // border mask
    float mx = sigm(xq + 0.5f) * (1.0f - sigm(xq - ((float)W_ - 0.5f)));
    float my = sigm(yq + 0.5f) * (1.0f - sigm(yq - ((float)H_ - 0.5f)));
    float bmask = mx * my;

    // bilinear taps
    float x0f = floorf(xq), y0f = floorf(yq);
    float wx = xq - x0f, wy = yq - y0f;
    int x0 = (int)x0f, y0 = (int)y0f;
    int x1 = x0 + 1,   y1 = y0 + 1;
    float vx0 = (x0 >= 0 && x0 <= W_ - 1) ? 1.0f : 0.0f;
    float vx1 = (x1 >= 0 && x1 <= W_ - 1) ? 1.0f : 0.0f;
    float vy0 = (y0 >= 0 && y0 <= H_ - 1) ? 1.0f : 0.0f;
    float vy1 = (y1 >= 0 && y1 <= H_ - 1) ? 1.0f : 0.0f;
    float w00 = (1.0f - wx) * (1.0f - wy) * vx0 * vy0;
    float w10 = wx * (1.0f - wy) * vx1 * vy0;
    float w01 = (1.0f - wx) * wy * vx0 * vy1;
    float w11 = wx * wy * vx1 * vy1;
    int xc0 = min(max(x0, 0), W_ - 1), xc1 = min(max(x1, 0), W_ - 1);
    int yc0 = min(max(y0, 0), H_ - 1), yc1 = min(max(y1, 0), H_ - 1);
    int o00 = yc0 * W_ + xc0, o10 = yc0 * W_ + xc1;
    int o01 = yc1 * W_ + xc0, o11 = yc1 * W_ + xc1;

    // warp flow_b (2 channels)
    const float* fb0 = flow_b + (size_t)b * 2 * HW_;
    const float* fb1 = fb0 + HW_;
    float fw0 = w00 * fb0[o00] + w10 * fb0[o10] + w01 * fb0[o01] + w11 * fb0[o11];
    float fw1 = w00 * fb1[o00] + w10 * fb1[o10] + w01 * fb1[o01] + w11 * fb1[o11];

    float mag = fa0 * fa0 + fa1 * fa1 + fw0 * fw0 + fw1 * fw1;
    float d0 = fa0 + fw0, d1 = fa1 + fw1;
    float D = d0 * d0 + d1 * d1;
    float occ = 1.0f - sigm(D - (0.01f * mag + 0.5f));
    float m = bmask * occ;
    g_mask[p] = m;

    // warp img_b (3 channels); store diff to scratch + data term
    const float* ib = img_b + (size_t)b * 3 * HW_;
    const float* ia = img_a + (size_t)b * 3 * HW_;
    float* dw = g_diff + (size_t)b * 3 * HW_ + r;
    float A = 0.0f;
#pragma unroll
    for (int c = 0; c < 3; c++) {
        const float* ibc = ib + c * HW_;
        float v = w00 * ibc[o00] + w10 * ibc[o10] + w01 * ibc[o01] + w11 * ibc[o11];
        float dd = ia[c * HW_ + r] - v;
        dw[c * HW_] = dd;
        A += dd * dd;
    }

    float e = (1.0f - m)
            + sqrtf(A + 1e-5f) * m
            + sqrtf(D + 1e-5f) * m;

    // smoothness
    float s = 0.0f;
    if (x < W_ - 1) {
        float a0 = flow_a[base2 + 1] - fa0;
        float a1 = flow_a[base2 + HW_ + 1] - fa1;
        s += a0 * a0 + a1 * a1;
    }
    if (y < H_ - 1) {
        float a0 = flow_a[base2 + W_] - fa0;
        float a1 = flow_a[base2 + HW_ + W_] - fa1;
        s += a0 * a0 + a1 * a1;
    }
    e += sqrtf(s + 1e-5f);

    blockReduceAdd(&g_acc[0], e);
}

// Pass 3: 5-tap gradient-constancy term on the stored diff (filter linearity).
// 256-thread blocks, 2 rows per block, 4 px/thread via float4.
__global__ void grad_kernel() {
    int sub = threadIdx.x >> 7;                 // 0 or 1: which row in block
    int row = blockIdx.x * 2 + sub;             // b*H + y
    int b = row / H_;
    int y = row - b * H_;
    int x = (threadIdx.x & 127) * 4;
    int rbase = y * W_ + x;

    const float* dp = g_diff + (size_t)b * 3 * HW_;
    float m[4];
    ld4a(g_mask + (size_t)b * HW_ + rbase, m);

    bool hasL  = (x >= 4);
    bool hasR  = (x + 4 < W_);
    bool hasU2 = (y >= 2), hasU1 = (y >= 1);
    bool hasD1 = (y + 1 < H_), hasD2 = (y + 2 < H_);

    float Ct[4] = {0.0f, 0.0f, 0.0f, 0.0f};
#pragma unroll
    for (int c = 0; c < 3; c++) {
        const float* Dc = dp + c * HW_;
        int o = rbase;
        float dC[4], dL[4], dR[4], dU2[4], dU1[4], dD1[4], dD2[4];
        ld4a(Dc + o, dC);
        if (hasL)  ld4a(Dc + o - 4, dL);           else zero4(dL);
        if (hasR)  ld4a(Dc + o + 4, dR);           else zero4(dR);
        if (hasU2) ld4a(Dc + o - 2 * W_, dU2);     else zero4(dU2);
        if (hasU1) ld4a(Dc + o - W_,     dU1);     else zero4(dU1);
        if (hasD1) ld4a(Dc + o + W_,     dD1);     else zero4(dD1);
        if (hasD2) ld4a(Dc + o + 2 * W_, dD2);     else zero4(dD2);

        float gx0 = K0 * dL[2] + K1 * dL[3] + K3 * dC[1] + K4 * dC[2];
        float gx1 = K0 * dL[3] + K1 * dC[0] + K3 * dC[2] + K4 * dC[3];
        float gx2 = K0 * dC[0] + K1 * dC[1] + K3 * dC[3] + K4 * dR[0];
        float gx3 = K0 * dC[1] + K1 * dC[2] + K3 * dR[0] + K4 * dR[1];
        Ct[0] += gx0 * gx0; Ct[1] += gx1 * gx1;
        Ct[2] += gx2 * gx2; Ct[3] += gx3 * gx3;

#pragma unroll
        for (int i = 0; i < 4; i++) {
            float gy = K0 * dU2[i] + K1 * dU1[i] + K3 * dD1[i] + K4 * dD2[i];
            Ct[i] += gy * gy;
        }
    }

    float e = 0.0f;
#pragma unroll
    for (int i = 0; i < 4; i++) e += sqrtf(Ct[i] + 1e-5f) * m[i];

    blockReduceAdd(&g_acc[0], e);
}

__global__ void finalize_kernel(float* __restrict__ out) {
    if (threadIdx.x == 0) {
        double energy  = g_acc[0];
        double entropy = 0.5 * g_acc[1];
        out[0] = (float)((energy - entropy) / (double)B_);
        out[1] = (float)(g_acc[2] / (double)NPIX);
    }
}

extern "C" void kernel_launch(void* const* d_in, const int* in_sizes, int n_in,
                              void* d_out, int out_size) {
    const float* meanf   = (const float*)d_in[0];
    const float* logvarf = (const float*)d_in[1];
    const float* meanb   = (const float*)d_in[2];
    const float* logvarb = (const float*)d_in[3];
    const float* img1    = (const float*)d_in[4];
    const float* img2    = (const float*)d_in[5];
    const float* target  = (const float*)d_in[6];
    const float* noisef  = (const float*)d_in[7];
    const float* noiseb  = (const float*)d_in[8];
    float* out = (float*)d_out;

    zero_acc_kernel<<<1, 32>>>();
    sample_kernel<<<NPIX / 4 / 256, 256>>>(meanf, logvarf, noisef,
                                           meanb, logvarb, noiseb, target);
    dir_kernel<<<NPIX / 256, 256>>>(img1, img2, 0);
    grad_kernel<<<B_ * H_ / 2, 256>>>();
    dir_kernel<<<NPIX / 256, 256>>>(img2, img1, 1);
    grad_kernel<<<B_ * H_ / 2, 256>>>();
    finalize_kernel<<<1, 32>>>(out);
}

// round 5
// speedup vs baseline: 1.4149x; 1.0028x over previous
#include <cuda_runtime.h>
#include <math.h>

#define B_  8
#define H_  384
#define W_  512
#define HW_ (H_ * W_)
#define NPIX (B_ * HW_)

#define K0 (-1.0f / 12.0f)
#define K1 (2.0f / 3.0f)
#define K3 (-2.0f / 3.0f)
#define K4 (1.0f / 12.0f)

// ---- scratch ----
// flows stored interleaved: [B][HW][2] so gathers are 64-bit
__device__ __align__(16) float  g_flowf[B_ * HW_ * 2];
__device__ __align__(16) float  g_flowb[B_ * HW_ * 2];
__device__ __align__(16) float  g_diff [B_ * 3 * HW_];   // img_a - warp(img_b)
__device__ __align__(16) float  g_mask [NPIX];
__device__ double g_acc[3];   // 0 = energy, 1 = entropy-sum, 2 = epe-sum

__device__ __forceinline__ float sigm(float x) { return 1.0f / (1.0f + __expf(-x)); }

__device__ __forceinline__ void ld4a(const float* __restrict__ p, float* a) {
    float4 v = *reinterpret_cast<const float4*>(p);
    a[0] = v.x; a[1] = v.y; a[2] = v.z; a[3] = v.w;
}
__device__ __forceinline__ void st4a(float* p, const float* a) {
    float4 v; v.x = a[0]; v.y = a[1]; v.z = a[2]; v.w = a[3];
    *reinterpret_cast<float4*>(p) = v;
}
__device__ __forceinline__ void zero4(float* d) { d[0]=d[1]=d[2]=d[3]=0.0f; }

__device__ __forceinline__ void blockReduceAdd(double* dst, float v) {
    __shared__ float ws[32];
    int lane = threadIdx.x & 31;
    int wid  = threadIdx.x >> 5;
#pragma unroll
    for (int o = 16; o; o >>= 1) v += __shfl_down_sync(0xffffffffu, v, o);
    __syncthreads();
    if (lane == 0) ws[wid] = v;
    __syncthreads();
    if (wid == 0) {
        int nw = (blockDim.x + 31) >> 5;
        v = (lane < nw) ? ws[lane] : 0.0f;
#pragma unroll
        for (int o = 16; o; o >>= 1) v += __shfl_down_sync(0xffffffffu, v, o);
        if (lane == 0) atomicAdd(dst, (double)v);
    }
}

__global__ void zero_acc_kernel() {
    if (threadIdx.x < 3) g_acc[threadIdx.x] = 0.0;
}

// Pass 1: flow samples (interleaved out) + entropy + EPE, 4 px/thread
__global__ void sample_kernel(const float* __restrict__ mf, const float* __restrict__ lvf,
                              const float* __restrict__ nf,
                              const float* __restrict__ mb, const float* __restrict__ lvb,
                              const float* __restrict__ nb,
                              const float* __restrict__ tgt) {
    int t = blockIdx.x * blockDim.x + threadIdx.x;     // 0 .. NPIX/4-1 exactly
    int b  = t / (HW_ / 4);
    int r4 = t - b * (HW_ / 4);
    int i0 = b * 2 * HW_ + r4 * 4;     // planar ch0 index
    int i1 = i0 + HW_;                  // planar ch1 index
    int oi = (b * HW_ + r4 * 4) * 2;    // interleaved index

    float m0[4], m1[4], l0[4], l1[4], n0[4], n1[4], t0[4], t1[4];
    ld4a(mf  + i0, m0); ld4a(mf  + i1, m1);
    ld4a(lvf + i0, l0); ld4a(lvf + i1, l1);
    ld4a(nf  + i0, n0); ld4a(nf  + i1, n1);
    ld4a(tgt + i0, t0); ld4a(tgt + i1, t1);

    float fo[8];
    float ent = 0.0f, epe = 0.0f;
#pragma unroll
    for (int i = 0; i < 4; i++) {
        fo[2 * i]     = m0[i] + __expf(0.5f * l0[i]) * n0[i];
        fo[2 * i + 1] = m1[i] + __expf(0.5f * l1[i]) * n1[i];
        ent += l0[i] + l1[i];
        float d0 = m0[i] - t0[i], d1 = m1[i] - t1[i];
        epe += sqrtf(d0 * d0 + d1 * d1);
    }
    st4a(g_flowf + oi, fo); st4a(g_flowf + oi + 4, fo + 4);

    ld4a(mb  + i0, m0); ld4a(mb  + i1, m1);
    ld4a(lvb + i0, l0); ld4a(lvb + i1, l1);
    ld4a(nb  + i0, n0); ld4a(nb  + i1, n1);
#pragma unroll
    for (int i = 0; i < 4; i++) {
        fo[2 * i]     = m0[i] + __expf(0.5f * l0[i]) * n0[i];
        fo[2 * i + 1] = m1[i] + __expf(0.5f * l1[i]) * n1[i];
        ent += l0[i] + l1[i];
    }
    st4a(g_flowb + oi, fo); st4a(g_flowb + oi + 4, fo + 4);

    blockReduceAdd(&g_acc[1], ent);
    blockReduceAdd(&g_acc[2], epe);
}

// Pass 2 (per direction): 1 px/thread. Stores mask + photometric diff.
__global__ void dir_kernel(const float* __restrict__ img_a,
                           const float* __restrict__ img_b, int dirn) {
    const float* __restrict__ flow_a = dirn ? g_flowb : g_flowf;
    const float* __restrict__ flow_b = dirn ? g_flowf : g_flowb;
    int p = blockIdx.x * blockDim.x + threadIdx.x;
    int b = p / HW_;
    int r = p - b * HW_;
    int y = r / W_;
    int x = r - y * W_;

    const float* fap = flow_a + (size_t)(b * HW_) * 2;
    float2 fav = *reinterpret_cast<const float2*>(fap + (size_t)r * 2);
    float fa0 = fav.x, fa1 = fav.y;
    float xq = (float)x + fa0;
    float yq = (float)y + fa1;

    // border mask
    float mx = sigm(xq + 0.5f) * (1.0f - sigm(xq - ((float)W_ - 0.5f)));
    float my = sigm(yq + 0.5f) * (1.0f - sigm(yq - ((float)H_ - 0.5f)));
    float bmask = mx * my;

    // bilinear taps
    float x0f = floorf(xq), y0f = floorf(yq);
    float wx = xq - x0f, wy = yq - y0f;
    int x0 = (int)x0f, y0 = (int)y0f;
    int x1 = x0 + 1,   y1 = y0 + 1;
    float vx0 = (x0 >= 0 && x0 <= W_ - 1) ? 1.0f : 0.0f;
    float vx1 = (x1 >= 0 && x1 <= W_ - 1) ? 1.0f : 0.0f;
    float vy0 = (y0 >= 0 && y0 <= H_ - 1) ? 1.0f : 0.0f;
    float vy1 = (y1 >= 0 && y1 <= H_ - 1) ? 1.0f : 0.0f;
    float w00 = (1.0f - wx) * (1.0f - wy) * vx0 * vy0;
    float w10 = wx * (1.0f - wy) * vx1 * vy0;
    float w01 = (1.0f - wx) * wy * vx0 * vy1;
    float w11 = wx * wy * vx1 * vy1;
    int xc0 = min(max(x0, 0), W_ - 1), xc1 = min(max(x1, 0), W_ - 1);
    int yc0 = min(max(y0, 0), H_ - 1), yc1 = min(max(y1, 0), H_ - 1);
    int o00 = yc0 * W_ + xc0, o10 = yc0 * W_ + xc1;
    int o01 = yc1 * W_ + xc0, o11 = yc1 * W_ + xc1;

    // warp flow_b: 4 x 64-bit gathers
    const float* fbp = flow_b + (size_t)(b * HW_) * 2;
    float2 g00 = *reinterpret_cast<const float2*>(fbp + (size_t)o00 * 2);
    float2 g10 = *reinterpret_cast<const float2*>(fbp + (size_t)o10 * 2);
    float2 g01 = *reinterpret_cast<const float2*>(fbp + (size_t)o01 * 2);
    float2 g11 = *reinterpret_cast<const float2*>(fbp + (size_t)o11 * 2);
    float fw0 = w00 * g00.x + w10 * g10.x + w01 * g01.x + w11 * g11.x;
    float fw1 = w00 * g00.y + w10 * g10.y + w01 * g01.y + w11 * g11.y;

    float mag = fa0 * fa0 + fa1 * fa1 + fw0 * fw0 + fw1 * fw1;
    float d0 = fa0 + fw0, d1 = fa1 + fw1;
    float D = d0 * d0 + d1 * d1;
    float occ = 1.0f - sigm(D - (0.01f * mag + 0.5f));
    float m = bmask * occ;
    g_mask[p] = m;

    // warp img_b (3 planar channels); store diff + data term
    const float* ib = img_b + (size_t)b * 3 * HW_;
    const float* ia = img_a + (size_t)b * 3 * HW_;
    float* dw = g_diff + (size_t)b * 3 * HW_ + r;
    float A = 0.0f;
#pragma unroll
    for (int c = 0; c < 3; c++) {
        const float* ibc = ib + c * HW_;
        float v = w00 * ibc[o00] + w10 * ibc[o10] + w01 * ibc[o01] + w11 * ibc[o11];
        float dd = ia[c * HW_ + r] - v;
        dw[c * HW_] = dd;
        A += dd * dd;
    }

    float e = (1.0f - m)
            + sqrtf(A + 1e-5f) * m
            + sqrtf(D + 1e-5f) * m;

    // smoothness (float2 neighbor loads)
    float s = 0.0f;
    if (x < W_ - 1) {
        float2 nx = *reinterpret_cast<const float2*>(fap + (size_t)(r + 1) * 2);
        float a0 = nx.x - fa0, a1 = nx.y - fa1;
        s += a0 * a0 + a1 * a1;
    }
    if (y < H_ - 1) {
        float2 nd = *reinterpret_cast<const float2*>(fap + (size_t)(r + W_) * 2);
        float a0 = nd.x - fa0, a1 = nd.y - fa1;
        s += a0 * a0 + a1 * a1;
    }
    e += sqrtf(s + 1e-5f);

    blockReduceAdd(&g_acc[0], e);
}

// Pass 3: 5-tap gradient-constancy on stored diff, with vertical register reuse.
// Thread handles a 4-row x 4-col column. Block = 256 threads = 8 rows x 512 cols.
__global__ void grad_kernel() {
    const int blocks_per_img = H_ / 8;                 // 48
    int b    = blockIdx.x / blocks_per_img;
    int ytl  = blockIdx.x - b * blocks_per_img;
    int rowg = threadIdx.x >> 7;                       // 0 or 1
    int y0   = ytl * 8 + rowg * 4;                     // first output row
    int x    = (threadIdx.x & 127) * 4;

    const float* dp = g_diff + (size_t)b * 3 * HW_;
    bool hasL = (x >= 4);
    bool hasR = (x + 4 < W_);

    float Ct[4][4];
#pragma unroll
    for (int i = 0; i < 4; i++) { Ct[i][0]=Ct[i][1]=Ct[i][2]=Ct[i][3]=0.0f; }

#pragma unroll
    for (int c = 0; c < 3; c++) {
        const float* Dc = dp + c * HW_ + x;
        // rolling 5-row window: w[k] = diff row (y0 - 2 + k)
        float w[5][4];
#pragma unroll
        for (int k = 0; k < 5; k++) {
            int yy = y0 - 2 + k;
            if (yy >= 0 && yy < H_) ld4a(Dc + yy * W_, w[k]); else zero4(w[k]);
        }
#pragma unroll
        for (int i = 0; i < 4; i++) {
            // y-stencil from window
#pragma unroll
            for (int j = 0; j < 4; j++) {
                float gy = K0 * w[0][j] + K1 * w[1][j] + K3 * w[3][j] + K4 * w[4][j];
                Ct[i][j] += gy * gy;
            }
            // x-stencil on center row w[2]
            int yy = y0 + i;
            float dL[4], dR[4];
            if (hasL) ld4a(Dc + yy * W_ - 4, dL); else zero4(dL);
            if (hasR) ld4a(Dc + yy * W_ + 4, dR); else zero4(dR);
            float gx0 = K0 * dL[2]   + K1 * dL[3]   + K3 * w[2][1] + K4 * w[2][2];
            float gx1 = K0 * dL[3]   + K1 * w[2][0] + K3 * w[2][2] + K4 * w[2][3];
            float gx2 = K0 * w[2][0] + K1 * w[2][1] + K3 * w[2][3] + K4 * dR[0];
            float gx3 = K0 * w[2][1] + K1 * w[2][2] + K3 * dR[0]   + K4 * dR[1];
            Ct[i][0] += gx0 * gx0; Ct[i][1] += gx1 * gx1;
            Ct[i][2] += gx2 * gx2; Ct[i][3] += gx3 * gx3;
            // shift window, load next row
#pragma unroll
            for (int k = 0; k < 4; k++) {
                w[k][0]=w[k+1][0]; w[k][1]=w[k+1][1]; w[k][2]=w[k+1][2]; w[k][3]=w[k+1][3];
            }
            int yn = y0 + i + 3;
            if (yn < H_) ld4a(Dc + yn * W_, w[4]); else zero4(w[4]);
        }
    }

    float e = 0.0f;
    const float* mp = g_mask + (size_t)b * HW_ + x;
#pragma unroll
    for (int i = 0; i < 4; i++) {
        float m[4];
        ld4a(mp + (y0 + i) * W_, m);
#pragma unroll
        for (int j = 0; j < 4; j++) e += sqrtf(Ct[i][j] + 1e-5f) * m[j];
    }

    blockReduceAdd(&g_acc[0], e);
}

__global__ void finalize_kernel(float* __restrict__ out) {
    if (threadIdx.x == 0) {
        double energy  = g_acc[0];
        double entropy = 0.5 * g_acc[1];
        out[0] = (float)((energy - entropy) / (double)B_);
        out[1] = (float)(g_acc[2] / (double)NPIX);
    }
}

extern "C" void kernel_launch(void* const* d_in, const int* in_sizes, int n_in,
                              void* d_out, int out_size) {
    const float* meanf   = (const float*)d_in[0];
    const float* logvarf = (const float*)d_in[1];
    const float* meanb   = (const float*)d_in[2];
    const float* logvarb = (const float*)d_in[3];
    const float* img1    = (const float*)d_in[4];
    const float* img2    = (const float*)d_in[5];
    const float* target  = (const float*)d_in[6];
    const float* noisef  = (const float*)d_in[7];
    const float* noiseb  = (const float*)d_in[8];
    float* out = (float*)d_out;

    zero_acc_kernel<<<1, 32>>>();
    sample_kernel<<<NPIX / 4 / 256, 256>>>(meanf, logvarf, noisef,
                                           meanb, logvarb, noiseb, target);
    dir_kernel<<<NPIX / 256, 256>>>(img1, img2, 0);
    grad_kernel<<<B_ * H_ / 8, 256>>>();
    dir_kernel<<<NPIX / 256, 256>>>(img2, img1, 1);
    grad_kernel<<<B_ * H_ / 8, 256>>>();
    finalize_kernel<<<1, 32>>>(out);
}